// round 10
// baseline (speedup 1.0000x reference)
#include <cuda_runtime.h>
#include <cuda_fp16.h>

// samples: (16,3,480,864) f32 ; encoded: (1,16,480,864) i32 ; n_pixels=2e6
// Both resizes are identity. Task: fp16-round -> segment mean -> gather.
// Output: float32 (values are fp16-rounded means).

#define N_PIX  2000000
#define T_DIM  16
#define H_DIM  480
#define W_DIM  864
#define HW     (H_DIM * W_DIM)        // 414720  (divisible by 8)
#define NPOS   (T_DIM * HW)           // 6635520
#define N_SAMP (T_DIM * 3 * HW)       // 19906560

// Accumulator: (sum_c0, sum_c1, sum_c2, count) per bucket.  32 MB.
__device__ float4 g_acc[N_PIX];

// ---------------------------------------------------------------------------
// 4 consecutive positions per thread (never cross t: HW%4==0).
// One red.global.add.v4.f32 per position (sum3 + count fused): 6.6M RMW ops.
// __ldcs on the streamed inputs keeps the L2 full of accumulator lines.
__global__ void scatter_kernel(const float* __restrict__ samples,
                               const int*   __restrict__ enc) {
    int j = blockIdx.x * blockDim.x + threadIdx.x;
    if (j >= NPOS / 4) return;
    int i = 4 * j;
    int t = i / HW;
    int p = i - t * HW;

    const float* s = samples + (size_t)t * 3 * HW + p;
    float4 c0 = __ldcs(reinterpret_cast<const float4*>(s));
    float4 c1 = __ldcs(reinterpret_cast<const float4*>(s + HW));
    float4 c2 = __ldcs(reinterpret_cast<const float4*>(s + 2 * HW));
    int4 idx4 = __ldcs(reinterpret_cast<const int4*>(enc + i));

    // fp16-round before accumulation (matches reference precision chain)
    #define R16(x) __half2float(__float2half_rn(x))
    float a0x = R16(c0.x), a0y = R16(c0.y), a0z = R16(c0.z), a0w = R16(c0.w);
    float a1x = R16(c1.x), a1y = R16(c1.y), a1z = R16(c1.z), a1w = R16(c1.w);
    float a2x = R16(c2.x), a2y = R16(c2.y), a2z = R16(c2.z), a2w = R16(c2.w);
    #undef R16

    #define RED4(ix, v0, v1, v2)                                              \
        asm volatile("red.global.add.v4.f32 [%0], {%1, %2, %3, %4};"          \
                     :: "l"(&g_acc[ix]), "f"(v0), "f"(v1), "f"(v2), "f"(1.0f) \
                     : "memory")
    RED4(idx4.x, a0x, a1x, a2x);
    RED4(idx4.y, a0y, a1y, a2y);
    RED4(idx4.z, a0z, a1z, a2z);
    RED4(idx4.w, a0w, a1w, a2w);
    #undef RED4
}

// ---------------------------------------------------------------------------
// Fused finalize + gather: read raw float4 accumulator (16B/lane = one 32B
// sector, same cost as any table), divide, fp16-round, write f32 via __stcs
// (streaming: keep the accumulator table resident in L2).
// 8 positions per thread.
__global__ void gather_kernel(const int* __restrict__ enc,
                              float*     __restrict__ out) {
    int j = blockIdx.x * blockDim.x + threadIdx.x;
    if (j >= NPOS / 8) return;
    int i = 8 * j;
    int t = i / HW;
    int p = i - t * HW;

    int4 ia = __ldcs(reinterpret_cast<const int4*>(enc + i));
    int4 ib = __ldcs(reinterpret_cast<const int4*>(enc + i + 4));

    float4 a0 = __ldg(&g_acc[ia.x]);
    float4 a1 = __ldg(&g_acc[ia.y]);
    float4 a2 = __ldg(&g_acc[ia.z]);
    float4 a3 = __ldg(&g_acc[ia.w]);
    float4 a4 = __ldg(&g_acc[ib.x]);
    float4 a5 = __ldg(&g_acc[ib.y]);
    float4 a6 = __ldg(&g_acc[ib.z]);
    float4 a7 = __ldg(&g_acc[ib.w]);

    float* o = out + (size_t)t * 3 * HW + p;

    float r0[8], r1[8], r2[8];
    #define FIN(k, A) {                                                       \
        float inv = 1.0f / (A).w;  /* gathered idx always has count >= 1 */   \
        r0[k] = __half2float(__float2half_rn((A).x * inv));                   \
        r1[k] = __half2float(__float2half_rn((A).y * inv));                   \
        r2[k] = __half2float(__float2half_rn((A).z * inv));                   \
    }
    FIN(0, a0) FIN(1, a1) FIN(2, a2) FIN(3, a3)
    FIN(4, a4) FIN(5, a5) FIN(6, a6) FIN(7, a7)
    #undef FIN

    #define ST8(row, r)                                                       \
        __stcs(reinterpret_cast<float4*>(o + (row) * HW),                     \
               make_float4((r)[0], (r)[1], (r)[2], (r)[3]));                  \
        __stcs(reinterpret_cast<float4*>(o + (row) * HW + 4),                 \
               make_float4((r)[4], (r)[5], (r)[6], (r)[7]));
    ST8(0, r0) ST8(1, r1) ST8(2, r2)
    #undef ST8
}

// ---------------------------------------------------------------------------
extern "C" void kernel_launch(void* const* d_in, const int* in_sizes, int n_in,
                              void* d_out, int out_size) {
    const float* samples = nullptr;
    const int*   enc     = nullptr;
    for (int k = 0; k < n_in; k++) {
        if (in_sizes[k] == N_SAMP)    samples = (const float*)d_in[k];
        else if (in_sizes[k] == NPOS) enc     = (const int*)d_in[k];
    }
    float* out = (float*)d_out;

    // Zero the accumulator with a memset node (driver-optimal, ~full HBM BW).
    void* acc_ptr = nullptr;
    cudaGetSymbolAddress(&acc_ptr, g_acc);
    cudaMemsetAsync(acc_ptr, 0, (size_t)N_PIX * sizeof(float4));

    const int TPB = 256;
    scatter_kernel<<<(NPOS / 4 + TPB - 1) / TPB, TPB>>>(samples, enc);
    gather_kernel<<<(NPOS / 8 + TPB - 1) / TPB, TPB>>>(enc, out);
}